// round 5
// baseline (speedup 1.0000x reference)
#include <cuda_runtime.h>
#include <math.h>

#define NB 512
#define NT 256
#define NZ 128
#define NX 64
#define NR 1024
#define G1 296          // persistent grid: 2 blocks/SM on >=148 SMs, all co-resident
#define R2 16           // phase-2 rows per block

// ---------------- device scratch (static: no allocation allowed) ----------------
__device__ float g_h[NB * NR];
__device__ float g_z[NB * NZ];
__device__ float g_rz[NB * 2048];       // r,z gate pre-activations (gi+gh summed)
__device__ float g_in[NB * NR];         // i_n
__device__ float g_hn[NB * NR];         // h_n
__device__ float g_hid[NB * 2048];      // [hid_gate | hid_prop]
__device__ float g_loclin[NB * NZ];
__device__ float g_gp[4 * NB * NZ];     // gate-pre partials (k-split 4)
__device__ float g_pp[4 * NB * NZ];     // prop partials
__device__ float g_zall[(size_t)NT * NB * NZ];   // [T,B,Z]
__device__ unsigned g_bar;

// ---------------- helpers ----------------
__device__ __forceinline__ float sigm(float x) { return 1.0f / (1.0f + expf(-x)); }
__device__ __forceinline__ float softplus_f(float x) {
    return fmaxf(x, 0.0f) + log1pf(expf(-fabsf(x)));
}

// Software grid barrier. Release: bar.sync + leader threadfence + atomic ticket.
// Acquire: volatile (L2) spin; all cross-block data is read with __ldcg afterwards.
__device__ __forceinline__ void gbar() {
    __syncthreads();
    if (threadIdx.x == 0) {
        __threadfence();
        unsigned t = atomicAdd(&g_bar, 1u);
        unsigned tgt = (t / G1 + 1u) * G1;
        while (*((volatile unsigned*)&g_bar) < tgt) { }
    }
    __syncthreads();
}

// ---------------- tile GEMM worker: 64x32 tile, BK=16, micro 4x2, 256 threads ----
// acc += A[bm:bm+64, :K] @ W[bn:bn+32, :K]^T   (A k-contig, W row-major [n,K])
// A is inter-block scratch -> __ldcg; W is read-only input -> plain (L1).
__device__ __forceinline__ void mm_acc(float acc[4][2],
                                       const float* __restrict__ A, int lda,
                                       const float* __restrict__ W, int ldw, int K,
                                       int bm, int bn,
                                       float (*As)[64], float (*Ws)[32])
{
    const int tid = threadIdx.x;
    const int tx = tid & 15, ty = tid >> 4;
    const int ar = tid >> 2, ac = (tid & 3) << 2;
    for (int k0 = 0; k0 < K; k0 += 16) {
        float4 va = __ldcg((const float4*)(A + (size_t)(bm + ar) * lda + k0 + ac));
        As[ac + 0][ar] = va.x; As[ac + 1][ar] = va.y;
        As[ac + 2][ar] = va.z; As[ac + 3][ar] = va.w;
        if (tid < 128) {
            float4 vw = *(const float4*)(W + (size_t)(bn + ar) * ldw + k0 + ac);
            Ws[ac + 0][ar] = vw.x; Ws[ac + 1][ar] = vw.y;
            Ws[ac + 2][ar] = vw.z; Ws[ac + 3][ar] = vw.w;
        }
        __syncthreads();
#pragma unroll
        for (int k = 0; k < 16; k++) {
            float4 a = *(const float4*)(&As[k][ty << 2]);
            float2 w = *(const float2*)(&Ws[k][tx << 1]);
            acc[0][0] += a.x * w.x; acc[0][1] += a.x * w.y;
            acc[1][0] += a.y * w.x; acc[1][1] += a.y * w.y;
            acc[2][0] += a.z * w.x; acc[2][1] += a.z * w.y;
            acc[3][0] += a.w * w.x; acc[3][1] += a.w * w.y;
        }
        __syncthreads();
    }
}

// ---------------- phase 1: the whole recurrence in ONE persistent kernel --------
__global__ void __launch_bounds__(256, 2) phase1_kernel(
    const float* __restrict__ eps,
    const float* __restrict__ w_ih, const float* __restrict__ b_ih,
    const float* __restrict__ w_hh, const float* __restrict__ b_hh,
    const float* __restrict__ tgw,  const float* __restrict__ tgb,
    const float* __restrict__ tghw, const float* __restrict__ tghb,
    const float* __restrict__ tpw,  const float* __restrict__ tpb,
    const float* __restrict__ tphw, const float* __restrict__ tphb,
    const float* __restrict__ tlw,  const float* __restrict__ tlb,
    const float* __restrict__ tsw,  const float* __restrict__ tsb)
{
    __shared__ float As[16][64];
    __shared__ float Ws[16][32];
    __shared__ float rp[2][128];
    const int bid = blockIdx.x, tid = threadIdx.x;
    const int tx = tid & 15, ty = tid >> 4;

    for (int t = 0; t < NT; t++) {
        // ---- S1: GRU gate pre-activations [512,3072], K = 1024 (h) + 128 (z) ----
        for (int tile = bid; tile < 768; tile += G1) {
            int mt = tile / 96, nt = tile % 96;
            int bm = mt << 6, bn = nt << 5;
            if (nt < 64) {  // r,z columns: store summed gi+gh
                float acc[4][2] = {};
                mm_acc(acc, g_h, NR, w_hh, NR, NR, bm, bn, As, Ws);
                mm_acc(acc, g_z, NZ, w_ih, NZ, NZ, bm, bn, As, Ws);
#pragma unroll
                for (int i = 0; i < 4; i++) {
                    int m = bm + (ty << 2) + i;
#pragma unroll
                    for (int j = 0; j < 2; j++) {
                        int n = bn + (tx << 1) + j;
                        g_rz[m * 2048 + n] = acc[i][j] + b_ih[n] + b_hh[n];
                    }
                }
            } else {        // n columns: need i_n and h_n separately
                float acc[4][2] = {};
                mm_acc(acc, g_z, NZ, w_ih, NZ, NZ, bm, bn, As, Ws);
#pragma unroll
                for (int i = 0; i < 4; i++) {
                    int m = bm + (ty << 2) + i;
#pragma unroll
                    for (int j = 0; j < 2; j++) {
                        int n = bn + (tx << 1) + j;
                        g_in[m * 1024 + (n - 2048)] = acc[i][j] + b_ih[n];
                    }
                }
                float acc2[4][2] = {};
                mm_acc(acc2, g_h, NR, w_hh, NR, NR, bm, bn, As, Ws);
#pragma unroll
                for (int i = 0; i < 4; i++) {
                    int m = bm + (ty << 2) + i;
#pragma unroll
                    for (int j = 0; j < 2; j++) {
                        int n = bn + (tx << 1) + j;
                        g_hn[m * 1024 + (n - 2048)] = acc2[i][j] + b_hh[n];
                    }
                }
            }
        }
        gbar();
        // ---- S2: GRU nonlinearity -> h_new ----
        for (int idx = bid * 256 + tid; idx < NB * NR; idx += G1 * 256) {
            int b = idx >> 10, j = idx & 1023;
            float r  = sigm(__ldcg(&g_rz[b * 2048 + j]));
            float zz = sigm(__ldcg(&g_rz[b * 2048 + 1024 + j]));
            float nn = tanhf(__ldcg(&g_in[idx]) + r * __ldcg(&g_hn[idx]));
            float hp = __ldcg(&g_h[idx]);
            g_h[idx] = (1.0f - zz) * nn + zz * hp;
        }
        gbar();
        // ---- S3: hid = relu(h @ [tgw;tpw]^T + b)  [512,2048]  +  loclin [512,128] ----
        for (int tile = bid; tile < 544; tile += G1) {
            if (tile < 512) {
                int mt = tile >> 6, nt = tile & 63;
                int bm = mt << 6, bn = nt << 5;
                const float* W; const float* bb; int nl;
                if (bn < 1024) { W = tgw; bb = tgb; nl = bn; }
                else           { W = tpw; bb = tpb; nl = bn - 1024; }
                float acc[4][2] = {};
                mm_acc(acc, g_h, NR, W, NR, NR, bm, nl, As, Ws);
#pragma unroll
                for (int i = 0; i < 4; i++) {
                    int m = bm + (ty << 2) + i;
#pragma unroll
                    for (int j = 0; j < 2; j++) {
                        int c = (tx << 1) + j;
                        g_hid[m * 2048 + bn + c] = fmaxf(acc[i][j] + bb[nl + c], 0.0f);
                    }
                }
            } else {
                int t2 = tile - 512;
                int bm = (t2 >> 2) << 6, bn = (t2 & 3) << 5;
                float acc[4][2] = {};
                mm_acc(acc, g_h, NR, tlw, NR, NR, bm, bn, As, Ws);
#pragma unroll
                for (int i = 0; i < 4; i++) {
                    int m = bm + (ty << 2) + i;
#pragma unroll
                    for (int j = 0; j < 2; j++) {
                        int n = bn + (tx << 1) + j;
                        g_loclin[m * 128 + n] = acc[i][j] + tlb[n];
                    }
                }
            }
        }
        gbar();
        // ---- S4: gatep/prop [512,128] K=1024, k-split by 4 for balance ----
        for (int tile = bid; tile < 256; tile += G1) {
            int g = tile >> 7;
            int rem = tile & 127;
            int bm = (rem >> 4) << 6;
            int bn = ((rem >> 2) & 3) << 5;
            int ks = rem & 3;
            const float* A = g_hid + (g ? 1024 : 0) + ks * 256;
            const float* W = (g ? tphw : tghw) + ks * 256;
            float acc[4][2] = {};
            mm_acc(acc, A, 2048, W, NR, 256, bm, bn, As, Ws);
            float* dst = (g ? g_pp : g_gp) + ks * (NB * NZ);
#pragma unroll
            for (int i = 0; i < 4; i++) {
                int m = bm + (ty << 2) + i;
#pragma unroll
                for (int j = 0; j < 2; j++) {
                    int n = bn + (tx << 1) + j;
                    dst[m * 128 + n] = acc[i][j];
                }
            }
        }
        gbar();
        // ---- S5: finalize z_t (reduce partials + fused scale GEMM + reparam) ----
        if (bid < 256) {
            int row = tid >> 7;              // 0/1
            int b = (bid << 1) + row;
            int i = tid & 127;
            float gp = tghb[i], pp = tphb[i];
#pragma unroll
            for (int ks = 0; ks < 4; ks++) {
                gp += __ldcg(&g_gp[ks * (NB * NZ) + b * 128 + i]);
                pp += __ldcg(&g_pp[ks * (NB * NZ) + b * 128 + i]);
            }
            rp[row][i] = fmaxf(pp, 0.0f);
            __syncthreads();
            float s = tsb[i];
            const float* wr = tsw + (size_t)i * 128;
            const float* rpr = rp[row];
#pragma unroll 8
            for (int j = 0; j < 128; j += 4) {
                float4 w = *(const float4*)(wr + j);
                s += rpr[j] * w.x + rpr[j + 1] * w.y + rpr[j + 2] * w.z + rpr[j + 3] * w.w;
            }
            float gate = sigm(gp);
            float loc = (1.0f - gate) * __ldcg(&g_loclin[b * 128 + i]) + gate * pp;
            float zv = loc + softplus_f(s) * eps[((size_t)b * NT + t) * NZ + i];
            g_z[b * 128 + i] = zv;
            g_zall[((size_t)t * NB + b) * NZ + i] = zv;
        }
        gbar();
    }
}

// ---------------- phase 2: obs transformer, fully fused per-row ----------------
__device__ __forceinline__ void obs_path(float acc[4],
                                         const float* __restrict__ wih,
                                         const float* __restrict__ bih,
                                         const float* __restrict__ whz,
                                         float (*zs)[128], float (*hs)[512], int tid)
{
    const int i = tid & 63, rg = tid >> 6;
    for (int half = 0; half < 2; half++) {
        int u0 = half * 512 + tid * 2;
        const float* w0 = wih + (size_t)u0 * 128;
        const float* w1 = w0 + 128;
        float b0 = bih[u0], b1 = bih[u0 + 1];
        for (int rc = 0; rc < 2; rc++) {
            float a0[8], a1[8];
#pragma unroll
            for (int r = 0; r < 8; r++) { a0[r] = b0; a1[r] = b1; }
            for (int k = 0; k < 128; k += 4) {
                float4 wv0 = *(const float4*)(w0 + k);
                float4 wv1 = *(const float4*)(w1 + k);
#pragma unroll
                for (int r = 0; r < 8; r++) {
                    float4 zv = *(const float4*)&zs[rc * 8 + r][k];
                    a0[r] += zv.x * wv0.x + zv.y * wv0.y + zv.z * wv0.z + zv.w * wv0.w;
                    a1[r] += zv.x * wv1.x + zv.y * wv1.y + zv.z * wv1.z + zv.w * wv1.w;
                }
            }
            int uu = tid * 2;
#pragma unroll
            for (int r = 0; r < 8; r++) {
                hs[rc * 8 + r][uu]     = fmaxf(a0[r], 0.0f);
                hs[rc * 8 + r][uu + 1] = fmaxf(a1[r], 0.0f);
            }
        }
        __syncthreads();
        const float* wr = whz + (size_t)i * 1024 + half * 512;
        for (int k = 0; k < 512; k += 4) {
            float4 wv = *(const float4*)(wr + k);
#pragma unroll
            for (int r4 = 0; r4 < 4; r4++) {
                const float* h = &hs[rg * 4 + r4][k];
                acc[r4] += h[0] * wv.x + h[1] * wv.y + h[2] * wv.z + h[3] * wv.w;
            }
        }
        __syncthreads();
    }
}

__global__ void __launch_bounds__(256) phase2_kernel(
    const float* __restrict__ ogw, const float* __restrict__ ogb,
    const float* __restrict__ oghw, const float* __restrict__ oghb,
    const float* __restrict__ opw, const float* __restrict__ opb,
    const float* __restrict__ ophw, const float* __restrict__ ophb,
    const float* __restrict__ olw, const float* __restrict__ olb,
    const float* __restrict__ osw, const float* __restrict__ osb,
    float* __restrict__ out)
{
    __shared__ float zs[R2][128];
    __shared__ float hs[R2][512];
    const int tid = threadIdx.x;
    const size_t base = (size_t)blockIdx.x * R2;   // global row = t*512 + b

    for (int idx = tid; idx < R2 * 128 / 4; idx += 256) {
        int r = idx >> 5, c = (idx & 31) << 2;
        *(float4*)&zs[r][c] = *(const float4*)&g_zall[(base + r) * 128 + c];
    }
    __syncthreads();

    const int i = tid & 63, rg = tid >> 6;
    float accg[4] = {0.f, 0.f, 0.f, 0.f};
    float accp[4] = {0.f, 0.f, 0.f, 0.f};
    obs_path(accg, ogw, ogb, oghw, zs, hs, tid);
    obs_path(accp, opw, opb, ophw, zs, hs, tid);

    float gate[4], prop[4];
    float (*ps)[64] = (float(*)[64])hs;   // reuse hs as relu(prop) [16][64]
#pragma unroll
    for (int r4 = 0; r4 < 4; r4++) {
        gate[r4] = sigm(accg[r4] + oghb[i]);
        prop[r4] = accp[r4] + ophb[i];
        ps[rg * 4 + r4][i] = fmaxf(prop[r4], 0.0f);
    }
    __syncthreads();

    float s[4], loc[4];
#pragma unroll
    for (int r4 = 0; r4 < 4; r4++) { s[r4] = osb[i]; loc[r4] = olb[i]; }
    const float* wsr = osw + (size_t)i * 64;
    for (int j = 0; j < 64; j += 4) {
        float4 wv = *(const float4*)(wsr + j);
#pragma unroll
        for (int r4 = 0; r4 < 4; r4++) {
            const float* p = &ps[rg * 4 + r4][j];
            s[r4] += p[0] * wv.x + p[1] * wv.y + p[2] * wv.z + p[3] * wv.w;
        }
    }
    const float* wlr = olw + (size_t)i * 128;
    for (int k = 0; k < 128; k += 4) {
        float4 wv = *(const float4*)(wlr + k);
#pragma unroll
        for (int r4 = 0; r4 < 4; r4++) {
            float4 zv = *(const float4*)&zs[rg * 4 + r4][k];
            loc[r4] += zv.x * wv.x + zv.y * wv.y + zv.z * wv.z + zv.w * wv.w;
        }
    }
#pragma unroll
    for (int r4 = 0; r4 < 4; r4++) {
        size_t gr = base + rg * 4 + r4;
        int tt = (int)(gr >> 9);
        int bb = (int)(gr & 511);
        float lo = (1.0f - gate[r4]) * loc[r4] + gate[r4] * prop[r4];
        float sc = softplus_f(s[r4]);
        out[((size_t)bb * NT + tt) * 128 + i]      = lo;
        out[((size_t)bb * NT + tt) * 128 + 64 + i] = sc;
    }
}

// ---------------- prep: init state + reset barrier ----------------
__global__ void prep_kernel(const float* __restrict__ z0, const float* __restrict__ h0)
{
    int idx = blockIdx.x * blockDim.x + threadIdx.x;
    if (idx == 0) g_bar = 0u;
    if (idx < NB * NR) g_h[idx] = h0[idx & (NR - 1)];
    if (idx < NB * NZ) g_z[idx] = z0[idx & (NZ - 1)];
}

// ---------------- host launcher: 3 graph nodes total ----------------
extern "C" void kernel_launch(void* const* d_in, const int* in_sizes, int n_in,
                              void* d_out, int out_size)
{
    (void)in_sizes; (void)n_in; (void)out_size;
    const float* eps      = (const float*)d_in[1];
    const float* z0       = (const float*)d_in[2];
    const float* h0       = (const float*)d_in[3];
    const float* gru_w_ih = (const float*)d_in[4];
    const float* gru_b_ih = (const float*)d_in[5];
    const float* gru_w_hh = (const float*)d_in[6];
    const float* gru_b_hh = (const float*)d_in[7];
    const float* tg_ih_w  = (const float*)d_in[8];
    const float* tg_ih_b  = (const float*)d_in[9];
    const float* tg_hz_w  = (const float*)d_in[10];
    const float* tg_hz_b  = (const float*)d_in[11];
    const float* tp_ih_w  = (const float*)d_in[12];
    const float* tp_ih_b  = (const float*)d_in[13];
    const float* tp_hz_w  = (const float*)d_in[14];
    const float* tp_hz_b  = (const float*)d_in[15];
    const float* tl_w     = (const float*)d_in[16];
    const float* tl_b     = (const float*)d_in[17];
    const float* ts_w     = (const float*)d_in[18];
    const float* ts_b     = (const float*)d_in[19];
    const float* og_ih_w  = (const float*)d_in[20];
    const float* og_ih_b  = (const float*)d_in[21];
    const float* og_hz_w  = (const float*)d_in[22];
    const float* og_hz_b  = (const float*)d_in[23];
    const float* op_ih_w  = (const float*)d_in[24];
    const float* op_ih_b  = (const float*)d_in[25];
    const float* op_hz_w  = (const float*)d_in[26];
    const float* op_hz_b  = (const float*)d_in[27];
    const float* ol_w     = (const float*)d_in[28];
    const float* ol_b     = (const float*)d_in[29];
    const float* os_w     = (const float*)d_in[30];
    const float* os_b     = (const float*)d_in[31];
    float* out = (float*)d_out;

    prep_kernel<<<(NB * NR + 255) / 256, 256>>>(z0, h0);
    phase1_kernel<<<G1, 256>>>(eps,
        gru_w_ih, gru_b_ih, gru_w_hh, gru_b_hh,
        tg_ih_w, tg_ih_b, tg_hz_w, tg_hz_b,
        tp_ih_w, tp_ih_b, tp_hz_w, tp_hz_b,
        tl_w, tl_b, ts_w, ts_b);
    phase2_kernel<<<(NT * NB) / R2, 256>>>(
        og_ih_w, og_ih_b, og_hz_w, og_hz_b,
        op_ih_w, op_ih_b, op_hz_w, op_hz_b,
        ol_w, ol_b, os_w, os_b, out);
}

// round 6
// speedup vs baseline: 1.1263x; 1.1263x over previous
#include <cuda_runtime.h>
#include <math.h>

#define NB 512
#define NT 256
#define NZ 128
#define NX 64
#define NR 1024
#define G1 296          // persistent grid: 2 blocks/SM on >=148 SMs, all co-resident
#define R2 16           // phase-2 rows per block

// ---------------- device scratch (static: no allocation allowed) ----------------
__device__ float g_h[NB * NR];
__device__ float g_z[NB * NZ];
__device__ float g_rz[NB * 2048];       // r,z gate pre-activations (gi+gh summed)
__device__ float g_in[NB * NR];         // i_n
__device__ float g_hn[NB * NR];         // h_n
__device__ float g_hid[NB * 2048];      // [hid_gate | hid_prop]
__device__ float g_loclin[NB * NZ];
__device__ float g_gp[4 * NB * NZ];     // gate-pre partials (k-split 4)
__device__ float g_pp[4 * NB * NZ];     // prop partials
__device__ float g_zall[(size_t)NT * NB * NZ];   // [T,B,Z]
__device__ unsigned g_bar;

// ---------------- helpers ----------------
__device__ __forceinline__ float sigm(float x) { return 1.0f / (1.0f + expf(-x)); }
__device__ __forceinline__ float softplus_f(float x) {
    return fmaxf(x, 0.0f) + log1pf(expf(-fabsf(x)));
}

// Software grid barrier. Release: bar.sync + leader threadfence + atomic ticket.
// Acquire: volatile (L2) spin; all cross-block data is read with __ldcg afterwards.
__device__ __forceinline__ void gbar() {
    __syncthreads();
    if (threadIdx.x == 0) {
        __threadfence();
        unsigned t = atomicAdd(&g_bar, 1u);
        unsigned tgt = (t / G1 + 1u) * G1;
        while (*((volatile unsigned*)&g_bar) < tgt) { }
    }
    __syncthreads();
}

// ---------------- tile GEMM worker: 64x32 tile, BK=16, micro 4x2, 256 threads ----
// Double-buffered: next chunk's LDGs are issued before the compute phase and
// stored to the alternate smem buffer after it -> L2 latency hidden, 1 sync/chunk.
// acc += A[bm:bm+64, :K] @ W[bn:bn+32, :K]^T   (A k-contig, W row-major [n,K])
// A is inter-block scratch -> __ldcg; W is read-only input -> plain (L1).
__device__ __forceinline__ void mm_acc(float acc[4][2],
                                       const float* __restrict__ A, int lda,
                                       const float* __restrict__ W, int ldw, int K,
                                       int bm, int bn,
                                       float (*As)[64], float (*Ws)[32])
{
    const int tid = threadIdx.x;
    const int tx = tid & 15, ty = tid >> 4;
    const int ar = tid >> 2, ac = (tid & 3) << 2;
    const float* Ap = A + (size_t)(bm + ar) * lda + ac;
    const float* Wp = W + (size_t)(bn + ar) * ldw + ac;
    const int nchunk = K >> 4;

    // prefetch chunk 0 -> buffer 0
    {
        float4 va = __ldcg((const float4*)Ap);
        As[ac + 0][ar] = va.x; As[ac + 1][ar] = va.y;
        As[ac + 2][ar] = va.z; As[ac + 3][ar] = va.w;
        if (tid < 128) {
            float4 vw = *(const float4*)Wp;
            Ws[ac + 0][ar] = vw.x; Ws[ac + 1][ar] = vw.y;
            Ws[ac + 2][ar] = vw.z; Ws[ac + 3][ar] = vw.w;
        }
    }
    __syncthreads();

    for (int c = 0; c < nchunk; c++) {
        const int buf = (c & 1) << 4;
        const int nbuf = buf ^ 16;
        float4 na, nw;
        const bool more = (c + 1 < nchunk);
        if (more) {
            na = __ldcg((const float4*)(Ap + (c + 1) * 16));
            if (tid < 128) nw = *(const float4*)(Wp + (c + 1) * 16);
        }
#pragma unroll
        for (int k = 0; k < 16; k++) {
            float4 a = *(const float4*)(&As[buf + k][ty << 2]);
            float2 w = *(const float2*)(&Ws[buf + k][tx << 1]);
            acc[0][0] += a.x * w.x; acc[0][1] += a.x * w.y;
            acc[1][0] += a.y * w.x; acc[1][1] += a.y * w.y;
            acc[2][0] += a.z * w.x; acc[2][1] += a.z * w.y;
            acc[3][0] += a.w * w.x; acc[3][1] += a.w * w.y;
        }
        if (more) {
            As[nbuf + ac + 0][ar] = na.x; As[nbuf + ac + 1][ar] = na.y;
            As[nbuf + ac + 2][ar] = na.z; As[nbuf + ac + 3][ar] = na.w;
            if (tid < 128) {
                Ws[nbuf + ac + 0][ar] = nw.x; Ws[nbuf + ac + 1][ar] = nw.y;
                Ws[nbuf + ac + 2][ar] = nw.z; Ws[nbuf + ac + 3][ar] = nw.w;
            }
        }
        __syncthreads();
    }
}

// ---------------- phase 1: the whole recurrence in ONE persistent kernel --------
__global__ void __launch_bounds__(256, 2) phase1_kernel(
    const float* __restrict__ eps,
    const float* __restrict__ w_ih, const float* __restrict__ b_ih,
    const float* __restrict__ w_hh, const float* __restrict__ b_hh,
    const float* __restrict__ tgw,  const float* __restrict__ tgb,
    const float* __restrict__ tghw, const float* __restrict__ tghb,
    const float* __restrict__ tpw,  const float* __restrict__ tpb,
    const float* __restrict__ tphw, const float* __restrict__ tphb,
    const float* __restrict__ tlw,  const float* __restrict__ tlb,
    const float* __restrict__ tsw,  const float* __restrict__ tsb)
{
    __shared__ float As[32][64];    // 2 buffers x 16 k
    __shared__ float Ws[32][32];
    __shared__ float rp[2][128];
    const int bid = blockIdx.x, tid = threadIdx.x;
    const int tx = tid & 15, ty = tid >> 4;

    for (int t = 0; t < NT; t++) {
        // ---- S1: GRU gate pre-activations [512,3072], K = 1024 (h) + 128 (z) ----
        for (int tile = bid; tile < 768; tile += G1) {
            int mt = tile / 96, nt = tile % 96;
            int bm = mt << 6, bn = nt << 5;
            if (nt < 64) {  // r,z columns: store summed gi+gh
                float acc[4][2] = {};
                mm_acc(acc, g_h, NR, w_hh, NR, NR, bm, bn, As, Ws);
                mm_acc(acc, g_z, NZ, w_ih, NZ, NZ, bm, bn, As, Ws);
#pragma unroll
                for (int i = 0; i < 4; i++) {
                    int m = bm + (ty << 2) + i;
#pragma unroll
                    for (int j = 0; j < 2; j++) {
                        int n = bn + (tx << 1) + j;
                        g_rz[m * 2048 + n] = acc[i][j] + b_ih[n] + b_hh[n];
                    }
                }
            } else {        // n columns: need i_n and h_n separately
                float acc[4][2] = {};
                mm_acc(acc, g_z, NZ, w_ih, NZ, NZ, bm, bn, As, Ws);
#pragma unroll
                for (int i = 0; i < 4; i++) {
                    int m = bm + (ty << 2) + i;
#pragma unroll
                    for (int j = 0; j < 2; j++) {
                        int n = bn + (tx << 1) + j;
                        g_in[m * 1024 + (n - 2048)] = acc[i][j] + b_ih[n];
                    }
                }
                float acc2[4][2] = {};
                mm_acc(acc2, g_h, NR, w_hh, NR, NR, bm, bn, As, Ws);
#pragma unroll
                for (int i = 0; i < 4; i++) {
                    int m = bm + (ty << 2) + i;
#pragma unroll
                    for (int j = 0; j < 2; j++) {
                        int n = bn + (tx << 1) + j;
                        g_hn[m * 1024 + (n - 2048)] = acc2[i][j] + b_hh[n];
                    }
                }
            }
        }
        gbar();
        // ---- S2: GRU nonlinearity -> h_new ----
        for (int idx = bid * 256 + tid; idx < NB * NR; idx += G1 * 256) {
            int b = idx >> 10, j = idx & 1023;
            float r  = sigm(__ldcg(&g_rz[b * 2048 + j]));
            float zz = sigm(__ldcg(&g_rz[b * 2048 + 1024 + j]));
            float nn = tanhf(__ldcg(&g_in[idx]) + r * __ldcg(&g_hn[idx]));
            float hp = __ldcg(&g_h[idx]);
            g_h[idx] = (1.0f - zz) * nn + zz * hp;
        }
        gbar();
        // ---- S3: hid = relu(h @ [tgw;tpw]^T + b)  [512,2048]  +  loclin [512,128] ----
        for (int tile = bid; tile < 544; tile += G1) {
            if (tile < 512) {
                int mt = tile >> 6, nt = tile & 63;
                int bm = mt << 6, bn = nt << 5;
                const float* W; const float* bb; int nl;
                if (bn < 1024) { W = tgw; bb = tgb; nl = bn; }
                else           { W = tpw; bb = tpb; nl = bn - 1024; }
                float acc[4][2] = {};
                mm_acc(acc, g_h, NR, W, NR, NR, bm, nl, As, Ws);
#pragma unroll
                for (int i = 0; i < 4; i++) {
                    int m = bm + (ty << 2) + i;
#pragma unroll
                    for (int j = 0; j < 2; j++) {
                        int c = (tx << 1) + j;
                        g_hid[m * 2048 + bn + c] = fmaxf(acc[i][j] + bb[nl + c], 0.0f);
                    }
                }
            } else {
                int t2 = tile - 512;
                int bm = (t2 >> 2) << 6, bn = (t2 & 3) << 5;
                float acc[4][2] = {};
                mm_acc(acc, g_h, NR, tlw, NR, NR, bm, bn, As, Ws);
#pragma unroll
                for (int i = 0; i < 4; i++) {
                    int m = bm + (ty << 2) + i;
#pragma unroll
                    for (int j = 0; j < 2; j++) {
                        int n = bn + (tx << 1) + j;
                        g_loclin[m * 128 + n] = acc[i][j] + tlb[n];
                    }
                }
            }
        }
        gbar();
        // ---- S4: gatep/prop [512,128] K=1024, k-split by 4 for balance ----
        for (int tile = bid; tile < 256; tile += G1) {
            int g = tile >> 7;
            int rem = tile & 127;
            int bm = (rem >> 4) << 6;
            int bn = ((rem >> 2) & 3) << 5;
            int ks = rem & 3;
            const float* A = g_hid + (g ? 1024 : 0) + ks * 256;
            const float* W = (g ? tphw : tghw) + ks * 256;
            float acc[4][2] = {};
            mm_acc(acc, A, 2048, W, NR, 256, bm, bn, As, Ws);
            float* dst = (g ? g_pp : g_gp) + ks * (NB * NZ);
#pragma unroll
            for (int i = 0; i < 4; i++) {
                int m = bm + (ty << 2) + i;
#pragma unroll
                for (int j = 0; j < 2; j++) {
                    int n = bn + (tx << 1) + j;
                    dst[m * 128 + n] = acc[i][j];
                }
            }
        }
        gbar();
        // ---- S5: finalize z_t (reduce partials + fused scale GEMM + reparam) ----
        if (bid < 256) {
            int row = tid >> 7;              // 0/1
            int b = (bid << 1) + row;
            int i = tid & 127;
            float gp = tghb[i], pp = tphb[i];
#pragma unroll
            for (int ks = 0; ks < 4; ks++) {
                gp += __ldcg(&g_gp[ks * (NB * NZ) + b * 128 + i]);
                pp += __ldcg(&g_pp[ks * (NB * NZ) + b * 128 + i]);
            }
            rp[row][i] = fmaxf(pp, 0.0f);
            __syncthreads();
            float s = tsb[i];
            const float* wr = tsw + (size_t)i * 128;
            const float* rpr = rp[row];
#pragma unroll 8
            for (int j = 0; j < 128; j += 4) {
                float4 w = *(const float4*)(wr + j);
                s += rpr[j] * w.x + rpr[j + 1] * w.y + rpr[j + 2] * w.z + rpr[j + 3] * w.w;
            }
            float gate = sigm(gp);
            float loc = (1.0f - gate) * __ldcg(&g_loclin[b * 128 + i]) + gate * pp;
            float zv = loc + softplus_f(s) * eps[((size_t)b * NT + t) * NZ + i];
            g_z[b * 128 + i] = zv;
            g_zall[((size_t)t * NB + b) * NZ + i] = zv;
        }
        gbar();
    }
}

// ---------------- phase 2: obs transformer, fully fused per-row ----------------
__device__ __forceinline__ void obs_path(float acc[4],
                                         const float* __restrict__ wih,
                                         const float* __restrict__ bih,
                                         const float* __restrict__ whz,
                                         float (*zs)[128], float (*hs)[512], int tid)
{
    const int i = tid & 63, rg = tid >> 6;
    for (int half = 0; half < 2; half++) {
        int u0 = half * 512 + tid * 2;
        const float* w0 = wih + (size_t)u0 * 128;
        const float* w1 = w0 + 128;
        float b0 = bih[u0], b1 = bih[u0 + 1];
        for (int rc = 0; rc < 2; rc++) {
            float a0[8], a1[8];
#pragma unroll
            for (int r = 0; r < 8; r++) { a0[r] = b0; a1[r] = b1; }
            for (int k = 0; k < 128; k += 4) {
                float4 wv0 = *(const float4*)(w0 + k);
                float4 wv1 = *(const float4*)(w1 + k);
#pragma unroll
                for (int r = 0; r < 8; r++) {
                    float4 zv = *(const float4*)&zs[rc * 8 + r][k];
                    a0[r] += zv.x * wv0.x + zv.y * wv0.y + zv.z * wv0.z + zv.w * wv0.w;
                    a1[r] += zv.x * wv1.x + zv.y * wv1.y + zv.z * wv1.z + zv.w * wv1.w;
                }
            }
            int uu = tid * 2;
#pragma unroll
            for (int r = 0; r < 8; r++) {
                hs[rc * 8 + r][uu]     = fmaxf(a0[r], 0.0f);
                hs[rc * 8 + r][uu + 1] = fmaxf(a1[r], 0.0f);
            }
        }
        __syncthreads();
        const float* wr = whz + (size_t)i * 1024 + half * 512;
        for (int k = 0; k < 512; k += 4) {
            float4 wv = *(const float4*)(wr + k);
#pragma unroll
            for (int r4 = 0; r4 < 4; r4++) {
                const float* h = &hs[rg * 4 + r4][k];
                acc[r4] += h[0] * wv.x + h[1] * wv.y + h[2] * wv.z + h[3] * wv.w;
            }
        }
        __syncthreads();
    }
}

__global__ void __launch_bounds__(256) phase2_kernel(
    const float* __restrict__ ogw, const float* __restrict__ ogb,
    const float* __restrict__ oghw, const float* __restrict__ oghb,
    const float* __restrict__ opw, const float* __restrict__ opb,
    const float* __restrict__ ophw, const float* __restrict__ ophb,
    const float* __restrict__ olw, const float* __restrict__ olb,
    const float* __restrict__ osw, const float* __restrict__ osb,
    float* __restrict__ out)
{
    __shared__ float zs[R2][128];
    __shared__ float hs[R2][512];
    const int tid = threadIdx.x;
    const size_t base = (size_t)blockIdx.x * R2;   // global row = t*512 + b

    for (int idx = tid; idx < R2 * 128 / 4; idx += 256) {
        int r = idx >> 5, c = (idx & 31) << 2;
        *(float4*)&zs[r][c] = *(const float4*)&g_zall[(base + r) * 128 + c];
    }
    __syncthreads();

    const int i = tid & 63, rg = tid >> 6;
    float accg[4] = {0.f, 0.f, 0.f, 0.f};
    float accp[4] = {0.f, 0.f, 0.f, 0.f};
    obs_path(accg, ogw, ogb, oghw, zs, hs, tid);
    obs_path(accp, opw, opb, ophw, zs, hs, tid);

    float gate[4], prop[4];
    float (*ps)[64] = (float(*)[64])hs;   // reuse hs as relu(prop) [16][64]
#pragma unroll
    for (int r4 = 0; r4 < 4; r4++) {
        gate[r4] = sigm(accg[r4] + oghb[i]);
        prop[r4] = accp[r4] + ophb[i];
        ps[rg * 4 + r4][i] = fmaxf(prop[r4], 0.0f);
    }
    __syncthreads();

    float s[4], loc[4];
#pragma unroll
    for (int r4 = 0; r4 < 4; r4++) { s[r4] = osb[i]; loc[r4] = olb[i]; }
    const float* wsr = osw + (size_t)i * 64;
    for (int j = 0; j < 64; j += 4) {
        float4 wv = *(const float4*)(wsr + j);
#pragma unroll
        for (int r4 = 0; r4 < 4; r4++) {
            const float* p = &ps[rg * 4 + r4][j];
            s[r4] += p[0] * wv.x + p[1] * wv.y + p[2] * wv.z + p[3] * wv.w;
        }
    }
    const float* wlr = olw + (size_t)i * 128;
    for (int k = 0; k < 128; k += 4) {
        float4 wv = *(const float4*)(wlr + k);
#pragma unroll
        for (int r4 = 0; r4 < 4; r4++) {
            float4 zv = *(const float4*)&zs[rg * 4 + r4][k];
            loc[r4] += zv.x * wv.x + zv.y * wv.y + zv.z * wv.z + zv.w * wv.w;
        }
    }
#pragma unroll
    for (int r4 = 0; r4 < 4; r4++) {
        size_t gr = base + rg * 4 + r4;
        int tt = (int)(gr >> 9);
        int bb = (int)(gr & 511);
        float lo = (1.0f - gate[r4]) * loc[r4] + gate[r4] * prop[r4];
        float sc = softplus_f(s[r4]);
        out[((size_t)bb * NT + tt) * 128 + i]      = lo;
        out[((size_t)bb * NT + tt) * 128 + 64 + i] = sc;
    }
}

// ---------------- prep: init state + reset barrier ----------------
__global__ void prep_kernel(const float* __restrict__ z0, const float* __restrict__ h0)
{
    int idx = blockIdx.x * blockDim.x + threadIdx.x;
    if (idx == 0) g_bar = 0u;
    if (idx < NB * NR) g_h[idx] = h0[idx & (NR - 1)];
    if (idx < NB * NZ) g_z[idx] = z0[idx & (NZ - 1)];
}

// ---------------- host launcher: 3 graph nodes total ----------------
extern "C" void kernel_launch(void* const* d_in, const int* in_sizes, int n_in,
                              void* d_out, int out_size)
{
    (void)in_sizes; (void)n_in; (void)out_size;
    const float* eps      = (const float*)d_in[1];
    const float* z0       = (const float*)d_in[2];
    const float* h0       = (const float*)d_in[3];
    const float* gru_w_ih = (const float*)d_in[4];
    const float* gru_b_ih = (const float*)d_in[5];
    const float* gru_w_hh = (const float*)d_in[6];
    const float* gru_b_hh = (const float*)d_in[7];
    const float* tg_ih_w  = (const float*)d_in[8];
    const float* tg_ih_b  = (const float*)d_in[9];
    const float* tg_hz_w  = (const float*)d_in[10];
    const float* tg_hz_b  = (const float*)d_in[11];
    const float* tp_ih_w  = (const float*)d_in[12];
    const float* tp_ih_b  = (const float*)d_in[13];
    const float* tp_hz_w  = (const float*)d_in[14];
    const float* tp_hz_b  = (const float*)d_in[15];
    const float* tl_w     = (const float*)d_in[16];
    const float* tl_b     = (const float*)d_in[17];
    const float* ts_w     = (const float*)d_in[18];
    const float* ts_b     = (const float*)d_in[19];
    const float* og_ih_w  = (const float*)d_in[20];
    const float* og_ih_b  = (const float*)d_in[21];
    const float* og_hz_w  = (const float*)d_in[22];
    const float* og_hz_b  = (const float*)d_in[23];
    const float* op_ih_w  = (const float*)d_in[24];
    const float* op_ih_b  = (const float*)d_in[25];
    const float* op_hz_w  = (const float*)d_in[26];
    const float* op_hz_b  = (const float*)d_in[27];
    const float* ol_w     = (const float*)d_in[28];
    const float* ol_b     = (const float*)d_in[29];
    const float* os_w     = (const float*)d_in[30];
    const float* os_b     = (const float*)d_in[31];
    float* out = (float*)d_out;

    prep_kernel<<<(NB * NR + 255) / 256, 256>>>(z0, h0);
    phase1_kernel<<<G1, 256>>>(eps,
        gru_w_ih, gru_b_ih, gru_w_hh, gru_b_hh,
        tg_ih_w, tg_ih_b, tg_hz_w, tg_hz_b,
        tp_ih_w, tp_ih_b, tp_hz_w, tp_hz_b,
        tl_w, tl_b, ts_w, ts_b);
    phase2_kernel<<<(NT * NB) / R2, 256>>>(
        og_ih_w, og_ih_b, og_hz_w, og_hz_b,
        op_ih_w, op_ih_b, op_hz_w, op_hz_b,
        ol_w, ol_b, os_w, os_b, out);
}